// round 9
// baseline (speedup 1.0000x reference)
#include <cuda_runtime.h>
#include <cuda_fp16.h>
#include <math.h>

// RandomLowRes2D fused kernel, v7: float4 blur tap loads (static alignment
// switch), pos-major fp16 LOW (row-wide LDS.128 upsample), 8 CTAs/SM.

#define HDIM 512
#define TW   8            // lanes (cross-axis) per CTA
#define HALO 16
#define AS   548          // A row stride (floats); 548 % 32 == 4, %4 == 0
#define NT   128

__device__ __forceinline__ int refl(int t) {
    t = (t < 0) ? (-1 - t) : t;
    return (t >= HDIM) ? (2 * HDIM - 1 - t) : t;
}

// Accumulate truncated-Gaussian blur at rows p1 (a0) and p1+1 (a1) from
// aligned float4 stream. D = (p1-R) & 3 alignment case, fully static.
template<int R, int D>
__device__ __forceinline__ void blur_acc(const float4* __restrict__ b4,
                                         const float* __restrict__ wr,
                                         float& a0, float& a1)
{
    constexpr int NL = (D + 2 * R + 1) / 4 + 1;   // float4 loads
    float s0 = 0.f, s1 = 0.f;
    #pragma unroll
    for (int t = 0; t < NL; t++) {
        float4 v = b4[t];
        #pragma unroll
        for (int q = 0; q < 4; q++) {
            const int k = 4 * t + q - D;          // tap index into sweep
            const float x = (q == 0) ? v.x : (q == 1) ? v.y : (q == 2) ? v.z : v.w;
            if (k >= 0 && k <= 2 * R)
                s0 += wr[(k <= R) ? k : 2 * R - k] * x;
            if (k >= 1 && k <= 2 * R + 1)
                s1 += wr[((k - 1) <= R) ? (k - 1) : 2 * R - (k - 1)] * x;
        }
    }
    a0 = s0; a1 = s1;
}

// Fused blur+downsample: LOW (pos-major fp16) gets one value per (j, lane).
template<int R>
__device__ __forceinline__ void blur_down(const float* __restrict__ A,
                                          __half* __restrict__ LOW,
                                          const float* __restrict__ w,
                                          float inv_wsum, float res,
                                          int n_low, int tid)
{
    float wr[R + 1];
    if (R == 0) {
        wr[0] = 1.0f;
    } else {
        #pragma unroll
        for (int k = 0; k <= R; k++) wr[k] = w[15 - R + k] * inv_wsum;
    }
    const int ntask = n_low * TW;
    for (int task = tid; task < ntask; task += NT) {
        int l = task & (TW - 1);
        int j = task >> 3;
        float pos = fminf((float)j * res, 511.0f);
        float lof = floorf(pos);
        float fr  = pos - lof;
        int   p1  = (int)lof;
        int   s   = p1 - R;                       // sweep start (may be <0)
        int   d   = s & 3;
        const float4* b4 = (const float4*)(A + l * AS + HALO + s - d);
        float a0, a1;
        switch (d) {
            case 0: blur_acc<R, 0>(b4, wr, a0, a1); break;
            case 1: blur_acc<R, 1>(b4, wr, a0, a1); break;
            case 2: blur_acc<R, 2>(b4, wr, a0, a1); break;
            default: blur_acc<R, 3>(b4, wr, a0, a1); break;
        }
        LOW[j * TW + l] = __float2half(a0 * (1.0f - fr) + a1 * fr);
    }
}

__global__ __launch_bounds__(NT, 8)
void lowres_kernel(const float* __restrict__ x,
                   const float* __restrict__ resolution,
                   const int*   __restrict__ axis,
                   const float* __restrict__ gap,
                   float* __restrict__ out)
{
    extern __shared__ float dynsm[];
    float*  A    = dynsm;                              // [TW][AS] fp32 + halo
    __half* LOW  = (__half*)(dynsm + TW * AS);         // [HDIM][TW] fp16 pos-major
    float*  pos2 = dynsm + TW * AS + (HDIM * TW) / 2;  // [HDIM]
    float*  w    = pos2 + HDIM;                        // [32]

    const int bid  = blockIdx.x;
    const int img  = bid & 63;
    const int tile = bid >> 6;
    const int tid  = threadIdx.x;

    const float res = resolution[img];
    const int   ax  = axis[img];
    const float sig = fmaxf(res * gap[img] * 0.42466090014400953f, 1e-6f);
    const int   R   = (sig < 0.18f) ? 0 : (sig < 0.6f) ? 3 : (sig < 1.4f) ? 7 : 15;

    const int   n_low = (int)fmaxf(floorf(512.0f / res), 1.0f);
    const float nl1   = (float)(n_low - 1);

    if (tid < 31) {
        float e = (float)(tid - 15) / sig;
        w[tid] = expf(-0.5f * e * e);
    }
    for (int i = tid; i < HDIM; i += NT)
        pos2[i] = fminf((float)i / res, nl1);

    const int base = tile * TW;
    const size_t ib = (size_t)img * HDIM * HDIM;
    const float* ip = x + ib;
    float*       op = out + ib;

    // ---- load slab into lane-major A (+ reflected halo) ----
    if (ax == 0) {
        const float4* ip4 = (const float4*)ip;
        for (int idx = tid; idx < HDIM * 2; idx += NT) {
            int l4 = idx & 1;
            int p  = idx >> 1;
            float4 v = ip4[p * (HDIM / 4) + (base >> 2) + l4];
            float* dst = A + (4 * l4) * AS + HALO + p;
            dst[0] = v.x; dst[AS] = v.y; dst[2 * AS] = v.z; dst[3 * AS] = v.w;
        }
    } else {
        for (int idx = tid; idx < TW * (HDIM / 4); idx += NT) {
            int v = idx & 127;
            int l = idx >> 7;
            float4 t = *(const float4*)(ip + (size_t)(base + l) * HDIM + 4 * v);
            *(float4*)(A + l * AS + HALO + 4 * v) = t;
        }
    }
    for (int idx = tid; idx < 2 * HALO * TW; idx += NT) {   // 256 halo elems
        int l = idx & (TW - 1);
        int h = idx >> 3;
        int t = (h < HALO) ? (h - HALO) : (HDIM + h - HALO);
        int rt = refl(t);
        float val = (ax == 0) ? ip[rt * HDIM + base + l]
                              : ip[(size_t)(base + l) * HDIM + rt];
        A[l * AS + HALO + t] = val;
    }
    __syncthreads();

    float inv_wsum = 1.0f;
    if (R > 0) {
        float s = 0.f;
        #pragma unroll
        for (int k = 0; k < 31; k++) s += w[k];
        inv_wsum = 1.0f / s;
    }

    // ---- fused blur + downsample -> LOW (fp16, pos-major) ----
    if      (R == 0)  blur_down<0>(A, LOW, w, inv_wsum, res, n_low, tid);
    else if (R == 3)  blur_down<3>(A, LOW, w, inv_wsum, res, n_low, tid);
    else if (R == 7)  blur_down<7>(A, LOW, w, inv_wsum, res, n_low, tid);
    else              blur_down<15>(A, LOW, w, inv_wsum, res, n_low, tid);
    __syncthreads();

    // ---- upsample + gmem stores ----
    if (ax == 0) {
        // one task per output row i: read full 8-lane low rows via LDS.128
        for (int i = tid; i < HDIM; i += NT) {
            float p2v = pos2[i];
            float l2  = floorf(p2v);
            float f   = p2v - l2;
            int j1 = min((int)l2, n_low - 1);
            int j2 = min(j1 + 1, n_low - 1);
            float omf = 1.0f - f;
            const __half2* r1 = (const __half2*)(LOW + j1 * TW);
            const __half2* r2 = (const __half2*)(LOW + j2 * TW);
            float4 o0, o1;
            {
                float2 a = __half22float2(r1[0]), b = __half22float2(r2[0]);
                o0.x = a.x * omf + b.x * f;  o0.y = a.y * omf + b.y * f;
                a = __half22float2(r1[1]); b = __half22float2(r2[1]);
                o0.z = a.x * omf + b.x * f;  o0.w = a.y * omf + b.y * f;
                a = __half22float2(r1[2]); b = __half22float2(r2[2]);
                o1.x = a.x * omf + b.x * f;  o1.y = a.y * omf + b.y * f;
                a = __half22float2(r1[3]); b = __half22float2(r2[3]);
                o1.z = a.x * omf + b.x * f;  o1.w = a.y * omf + b.y * f;
            }
            *(float4*)(op + (size_t)i * HDIM + base)     = o0;
            *(float4*)(op + (size_t)i * HDIM + base + 4) = o1;
        }
    } else {
        // task per (lane-pair lq, 4-column group v): half2 low reads
        for (int idx = tid; idx < 4 * (HDIM / 4); idx += NT) {
            int v  = idx & 127;
            int lq = idx >> 7;              // 0..3 -> lanes 2lq, 2lq+1
            const float4 pv = *(const float4*)(pos2 + 4 * v);
            float4 ra, rb;                  // lane 2lq, lane 2lq+1
            #pragma unroll
            for (int q = 0; q < 4; q++) {
                float p2v = (q == 0) ? pv.x : (q == 1) ? pv.y : (q == 2) ? pv.z : pv.w;
                float l2  = floorf(p2v);
                float f   = p2v - l2;
                int j1 = min((int)l2, n_low - 1);
                int j2 = min(j1 + 1, n_low - 1);
                float2 h1 = __half22float2(*(const __half2*)(LOW + j1 * TW + 2 * lq));
                float2 h2 = __half22float2(*(const __half2*)(LOW + j2 * TW + 2 * lq));
                float va = h1.x * (1.0f - f) + h2.x * f;
                float vb = h1.y * (1.0f - f) + h2.y * f;
                if (q == 0) { ra.x = va; rb.x = vb; }
                else if (q == 1) { ra.y = va; rb.y = vb; }
                else if (q == 2) { ra.z = va; rb.z = vb; }
                else { ra.w = va; rb.w = vb; }
            }
            *(float4*)(op + (size_t)(base + 2 * lq) * HDIM + 4 * v)     = ra;
            *(float4*)(op + (size_t)(base + 2 * lq + 1) * HDIM + 4 * v) = rb;
        }
    }
}

extern "C" void kernel_launch(void* const* d_in, const int* in_sizes, int n_in,
                              void* d_out, int out_size)
{
    const float* x   = (const float*)d_in[0];
    const float* res = (const float*)d_in[1];
    const int*   ax  = (const int*)d_in[2];
    const float* gp  = (const float*)d_in[3];
    float* out = (float*)d_out;

    const int n_img = in_sizes[1];   // 64
    // A(8*548 f32) + LOW(512*8 f16) + pos2(512 f32) + w(32 f32) = 27904 B
    const size_t smem = (size_t)(TW * AS) * 4 + (size_t)(HDIM * TW) * 2
                      + (size_t)HDIM * 4 + 32 * 4;

    cudaFuncSetAttribute(lowres_kernel,
                         cudaFuncAttributeMaxDynamicSharedMemorySize, (int)smem);

    dim3 grid((HDIM / TW) * n_img);  // 4096 CTAs, image-interleaved
    lowres_kernel<<<grid, NT, smem>>>(x, res, ax, gp, out);
}

// round 12
// speedup vs baseline: 1.1250x; 1.1250x over previous
#include <cuda_runtime.h>
#include <cuda_fp16.h>
#include <math.h>

// RandomLowRes2D fused kernel, v9: pos-major A (quad-swizzled, LDS.128 blur
// across lanes — static alignment), pos-major fp16 LOW (row-wide upsample),
// fused blur+downsample, 8 CTAs/SM, image-interleaved CTAs.

#define HDIM 512
#define TW   8            // lanes (cross-axis) per CTA
#define HALO 16
#define NROW (HDIM + 2 * HALO)   // 544 rows of 8 floats
#define NT   128

__device__ __forceinline__ int refl(int t) {
    t = (t < 0) ? (-1 - t) : t;
    return (t >= HDIM) ? (2 * HDIM - 1 - t) : t;
}

// quad swizzle bit for row
__device__ __forceinline__ int swz(int row) { return (row >> 2) & 1; }

// Fused blur+downsample. Task = (lane-quad q, low row j). Each window row is
// one LDS.128 (4 lanes); two accumulator sets (rows p1, p1+1) share loads.
template<int R>
__device__ __forceinline__ void blur_down(const float* __restrict__ A,
                                          __half* __restrict__ LOW,
                                          const float* __restrict__ w,
                                          float inv_wsum, float res,
                                          int n_low, int tid)
{
    float wr[R + 1];
    if (R == 0) wr[0] = 1.0f;
    else {
        #pragma unroll
        for (int k = 0; k <= R; k++) wr[k] = w[15 - R + k] * inv_wsum;
    }
    const float4* A4 = (const float4*)A;
    const int ntask = n_low * 2;
    for (int task = tid; task < ntask; task += NT) {
        int q = task & 1;
        int j = task >> 1;
        float pos = fminf((float)j * res, 511.0f);
        float lof = floorf(pos);
        float fr  = pos - lof;
        int   r0  = (int)lof - R + HALO;      // first physical row of sweep
        float4 a0 = make_float4(0.f, 0.f, 0.f, 0.f);
        float4 a1 = make_float4(0.f, 0.f, 0.f, 0.f);
        #pragma unroll
        for (int k = 0; k <= 2 * R + 1; k++) {
            int row = r0 + k;
            float4 v = A4[row * 2 + (q ^ swz(row))];
            if (k <= 2 * R) {
                float w0 = wr[(k <= R) ? k : 2 * R - k];
                a0.x = fmaf(w0, v.x, a0.x); a0.y = fmaf(w0, v.y, a0.y);
                a0.z = fmaf(w0, v.z, a0.z); a0.w = fmaf(w0, v.w, a0.w);
            }
            if (k >= 1) {
                int km = k - 1;
                float w1 = wr[(km <= R) ? km : 2 * R - km];
                a1.x = fmaf(w1, v.x, a1.x); a1.y = fmaf(w1, v.y, a1.y);
                a1.z = fmaf(w1, v.z, a1.z); a1.w = fmaf(w1, v.w, a1.w);
            }
        }
        float f0 = 1.0f - fr;
        __half2 h01 = __floats2half2_rn(a0.x * f0 + a1.x * fr,
                                        a0.y * f0 + a1.y * fr);
        __half2 h23 = __floats2half2_rn(a0.z * f0 + a1.z * fr,
                                        a0.w * f0 + a1.w * fr);
        __half2* dst = (__half2*)(LOW + j * TW + 4 * q);
        dst[0] = h01;
        dst[1] = h23;
    }
}

__global__ __launch_bounds__(NT, 8)
void lowres_kernel(const float* __restrict__ x,
                   const float* __restrict__ resolution,
                   const int*   __restrict__ axis,
                   const float* __restrict__ gap,
                   float* __restrict__ out)
{
    extern __shared__ float dynsm[];
    float*  A    = dynsm;                                // [NROW][8] fp32
    __half* LOW  = (__half*)(dynsm + NROW * TW);         // [HDIM][8] fp16
    float*  pos2 = dynsm + NROW * TW + (HDIM * TW) / 2;  // [HDIM]
    float*  w    = pos2 + HDIM;                          // [32]

    const int bid  = blockIdx.x;
    const int img  = bid & 63;          // interleave images across waves
    const int tile = bid >> 6;
    const int tid  = threadIdx.x;

    const float res = resolution[img];
    const int   ax  = axis[img];
    const float sig = fmaxf(res * gap[img] * 0.42466090014400953f, 1e-6f);
    const int   R   = (sig < 0.18f) ? 0 : (sig < 0.6f) ? 3 : (sig < 1.4f) ? 7 : 15;

    const int   n_low = (int)fmaxf(floorf(512.0f / res), 1.0f);
    const float nl1   = (float)(n_low - 1);

    if (tid < 31) {
        float e = (float)(tid - 15) / sig;
        w[tid] = expf(-0.5f * e * e);
    }
    for (int i = tid; i < HDIM; i += NT)
        pos2[i] = fminf((float)i / res, nl1);   // true division as reference

    const int base = tile * TW;
    const size_t ib = (size_t)img * HDIM * HDIM;
    const float* ip = x + ib;
    float*       op = out + ib;
    float4* A4 = (float4*)A;

    // ---- load slab into pos-major A (+ reflected halo) ----
    if (ax == 0) {
        const float4* ip4 = (const float4*)ip;
        for (int idx = tid; idx < HDIM * 2; idx += NT) {
            int l4 = idx & 1;
            int p  = idx >> 1;
            float4 v = ip4[p * (HDIM / 4) + (base >> 2) + l4];
            int row = p + HALO;
            A4[row * 2 + (l4 ^ swz(row))] = v;        // STS.128, conflict-free
        }
    } else {
        for (int idx = tid; idx < TW * (HDIM / 4); idx += NT) {
            int v = idx & 127;
            int l = idx >> 7;
            float4 t = *(const float4*)(ip + (size_t)(base + l) * HDIM + 4 * v);
            int lq = l >> 2, lc = l & 3;
            #pragma unroll
            for (int i = 0; i < 4; i++) {
                int row = 4 * v + i + HALO;
                float val = (i == 0) ? t.x : (i == 1) ? t.y : (i == 2) ? t.z : t.w;
                A[row * TW + 4 * (lq ^ swz(row)) + lc] = val;
            }
        }
    }
    for (int idx = tid; idx < 2 * HALO * TW; idx += NT) {   // 256 halo elems
        int l = idx & (TW - 1);
        int h = idx >> 3;
        int t = (h < HALO) ? (h - HALO) : (HDIM + h - HALO);
        int rt = refl(t);
        float val = (ax == 0) ? ip[rt * HDIM + base + l]
                              : ip[(size_t)(base + l) * HDIM + rt];
        int row = t + HALO;
        A[row * TW + 4 * ((l >> 2) ^ swz(row)) + (l & 3)] = val;
    }
    __syncthreads();

    float inv_wsum = 1.0f;
    if (R > 0) {
        float s = 0.f;
        #pragma unroll
        for (int k = 0; k < 31; k++) s += w[k];
        inv_wsum = 1.0f / s;
    }

    // ---- fused blur + downsample -> LOW (fp16, pos-major) ----
    if      (R == 0)  blur_down<0>(A, LOW, w, inv_wsum, res, n_low, tid);
    else if (R == 3)  blur_down<3>(A, LOW, w, inv_wsum, res, n_low, tid);
    else if (R == 7)  blur_down<7>(A, LOW, w, inv_wsum, res, n_low, tid);
    else              blur_down<15>(A, LOW, w, inv_wsum, res, n_low, tid);
    __syncthreads();

    // ---- upsample + gmem stores ----
    if (ax == 0) {
        for (int i = tid; i < HDIM; i += NT) {
            float p2v = pos2[i];
            float l2  = floorf(p2v);
            float f   = p2v - l2;
            int j1 = min((int)l2, n_low - 1);
            int j2 = min(j1 + 1, n_low - 1);
            float omf = 1.0f - f;
            float4 r1 = *(const float4*)(LOW + j1 * TW);   // whole 8-lane row
            float4 r2 = *(const float4*)(LOW + j2 * TW);
            const __half2* h1 = (const __half2*)&r1;
            const __half2* h2 = (const __half2*)&r2;
            float4 o0, o1;
            {
                float2 a = __half22float2(h1[0]), b = __half22float2(h2[0]);
                o0.x = a.x * omf + b.x * f;  o0.y = a.y * omf + b.y * f;
                a = __half22float2(h1[1]); b = __half22float2(h2[1]);
                o0.z = a.x * omf + b.x * f;  o0.w = a.y * omf + b.y * f;
                a = __half22float2(h1[2]); b = __half22float2(h2[2]);
                o1.x = a.x * omf + b.x * f;  o1.y = a.y * omf + b.y * f;
                a = __half22float2(h1[3]); b = __half22float2(h2[3]);
                o1.z = a.x * omf + b.x * f;  o1.w = a.y * omf + b.y * f;
            }
            *(float4*)(op + (size_t)i * HDIM + base)     = o0;
            *(float4*)(op + (size_t)i * HDIM + base + 4) = o1;
        }
    } else {
        for (int idx = tid; idx < 4 * (HDIM / 4); idx += NT) {
            int v  = idx & 127;
            int lq = idx >> 7;              // 0..3 -> lanes 2lq, 2lq+1
            const float4 pv = *(const float4*)(pos2 + 4 * v);
            float4 ra, rb;
            #pragma unroll
            for (int q = 0; q < 4; q++) {
                float p2v = (q == 0) ? pv.x : (q == 1) ? pv.y : (q == 2) ? pv.z : pv.w;
                float l2  = floorf(p2v);
                float f   = p2v - l2;
                int j1 = min((int)l2, n_low - 1);
                int j2 = min(j1 + 1, n_low - 1);
                float2 h1 = __half22float2(*(const __half2*)(LOW + j1 * TW + 2 * lq));
                float2 h2 = __half22float2(*(const __half2*)(LOW + j2 * TW + 2 * lq));
                float va = h1.x * (1.0f - f) + h2.x * f;
                float vb = h1.y * (1.0f - f) + h2.y * f;
                if (q == 0) { ra.x = va; rb.x = vb; }
                else if (q == 1) { ra.y = va; rb.y = vb; }
                else if (q == 2) { ra.z = va; rb.z = vb; }
                else { ra.w = va; rb.w = vb; }
            }
            *(float4*)(op + (size_t)(base + 2 * lq) * HDIM + 4 * v)     = ra;
            *(float4*)(op + (size_t)(base + 2 * lq + 1) * HDIM + 4 * v) = rb;
        }
    }
}

extern "C" void kernel_launch(void* const* d_in, const int* in_sizes, int n_in,
                              void* d_out, int out_size)
{
    const float* x   = (const float*)d_in[0];
    const float* res = (const float*)d_in[1];
    const int*   ax  = (const int*)d_in[2];
    const float* gp  = (const float*)d_in[3];
    float* out = (float*)d_out;

    const int n_img = in_sizes[1];   // 64
    // A(544*8 f32) + LOW(512*8 f16) + pos2(512 f32) + w(32 f32) = 27776 B
    const size_t smem = (size_t)(NROW * TW) * 4 + (size_t)(HDIM * TW) * 2
                      + (size_t)HDIM * 4 + 32 * 4;

    cudaFuncSetAttribute(lowres_kernel,
                         cudaFuncAttributeMaxDynamicSharedMemorySize, (int)smem);

    dim3 grid((HDIM / TW) * n_img);  // 4096 CTAs, image-interleaved
    lowres_kernel<<<grid, NT, smem>>>(x, res, ax, gp, out);
}

// round 13
// speedup vs baseline: 1.2195x; 1.0840x over previous
#include <cuda_runtime.h>
#include <cuda_fp16.h>
#include <math.h>

// RandomLowRes2D fused kernel, v10: fp16 pos-major A (pair-swizzled, half2
// blur loads = half the smem wavefronts), fp32 accumulation, fp16 pos-major
// LOW, 10 CTAs/SM, fused blur+downsample, image-interleaved CTAs.

#define HDIM 512
#define TW   8            // lanes (cross-axis) per CTA
#define HALO 16
#define NROW (HDIM + 2 * HALO)   // 544 rows of 8 halfs (16 B)
#define NT   128

__device__ __forceinline__ int refl(int t) {
    t = (t < 0) ? (-1 - t) : t;
    return (t >= HDIM) ? (2 * HDIM - 1 - t) : t;
}

// pair-position swizzle: spreads banks for row strides 1/2/4/8/16 (worst 2-way)
__device__ __forceinline__ int swz4(int row) {
    return (row + (row >> 2) + (row >> 4)) & 3;
}

// Fused blur+downsample. Task = (lane-pair q, low row j). Each tap row is one
// half2 load (4 B) feeding 2 outputs; accumulate fp32 at rows p1 and p1+1.
template<int R>
__device__ __forceinline__ void blur_down(const __half* __restrict__ A,
                                          __half* __restrict__ LOW,
                                          const float* __restrict__ w,
                                          float inv_wsum, float res,
                                          int n_low, int tid)
{
    float wr[R + 1];
    if (R == 0) wr[0] = 1.0f;
    else {
        #pragma unroll
        for (int k = 0; k <= R; k++) wr[k] = w[15 - R + k] * inv_wsum;
    }
    const int ntask = n_low * 4;
    for (int task = tid; task < ntask; task += NT) {
        int q = task & 3;
        int j = task >> 2;
        float pos = fminf((float)j * res, 511.0f);
        float lof = floorf(pos);
        float fr  = pos - lof;
        int   r0  = (int)lof - R + HALO;      // first physical row of sweep
        float a0x = 0.f, a0y = 0.f, a1x = 0.f, a1y = 0.f;
        #pragma unroll
        for (int k = 0; k <= 2 * R + 1; k++) {
            int row = r0 + k;
            __half2 hv = *(const __half2*)(A + row * TW + 2 * (q ^ swz4(row)));
            float2 v = __half22float2(hv);
            if (k <= 2 * R) {
                float w0 = wr[(k <= R) ? k : 2 * R - k];
                a0x = fmaf(w0, v.x, a0x);
                a0y = fmaf(w0, v.y, a0y);
            }
            if (k >= 1) {
                int km = k - 1;
                float w1 = wr[(km <= R) ? km : 2 * R - km];
                a1x = fmaf(w1, v.x, a1x);
                a1y = fmaf(w1, v.y, a1y);
            }
        }
        float f0 = 1.0f - fr;
        __half2 o = __floats2half2_rn(a0x * f0 + a1x * fr,
                                      a0y * f0 + a1y * fr);
        *(__half2*)(LOW + j * TW + 2 * q) = o;   // unswizzled, conflict-free
    }
}

__global__ __launch_bounds__(NT, 10)
void lowres_kernel(const float* __restrict__ x,
                   const float* __restrict__ resolution,
                   const int*   __restrict__ axis,
                   const float* __restrict__ gap,
                   float* __restrict__ out)
{
    extern __shared__ float dynsm[];
    __half* A    = (__half*)dynsm;                        // [NROW][8] fp16
    __half* LOW  = A + NROW * TW;                         // [HDIM][8] fp16
    float*  pos2 = (float*)(LOW + HDIM * TW);             // [HDIM]
    float*  w    = pos2 + HDIM;                           // [32]

    const int bid  = blockIdx.x;
    const int img  = bid & 63;          // interleave images across waves
    const int tile = bid >> 6;
    const int tid  = threadIdx.x;

    const float res = resolution[img];
    const int   ax  = axis[img];
    const float sig = fmaxf(res * gap[img] * 0.42466090014400953f, 1e-6f);
    const int   R   = (sig < 0.18f) ? 0 : (sig < 0.6f) ? 3 : (sig < 1.4f) ? 7 : 15;

    const int   n_low = (int)fmaxf(floorf(512.0f / res), 1.0f);
    const float nl1   = (float)(n_low - 1);

    if (tid < 31) {
        float e = (float)(tid - 15) / sig;
        w[tid] = expf(-0.5f * e * e);
    }
    for (int i = tid; i < HDIM; i += NT)
        pos2[i] = fminf((float)i / res, nl1);   // true division as reference

    const int base = tile * TW;
    const size_t ib = (size_t)img * HDIM * HDIM;
    const float* ip = x + ib;
    float*       op = out + ib;

    // ---- load slab into fp16 pos-major A (+ reflected halo) ----
    if (ax == 0) {
        const float4* ip4 = (const float4*)ip;
        for (int idx = tid; idx < HDIM * 2; idx += NT) {
            int l4 = idx & 1;                  // lanes 4*l4 .. 4*l4+3
            int p  = idx >> 1;
            float4 v = ip4[p * (HDIM / 4) + (base >> 2) + l4];
            int row = p + HALO;
            int s   = swz4(row);
            *(__half2*)(A + row * TW + 2 * ((2 * l4)     ^ s)) = __floats2half2_rn(v.x, v.y);
            *(__half2*)(A + row * TW + 2 * ((2 * l4 + 1) ^ s)) = __floats2half2_rn(v.z, v.w);
        }
    } else {
        for (int idx = tid; idx < TW * (HDIM / 4); idx += NT) {
            int v = idx & 127;
            int l = idx >> 7;
            float4 t = *(const float4*)(ip + (size_t)(base + l) * HDIM + 4 * v);
            int q = l >> 1, h = l & 1;
            #pragma unroll
            for (int i = 0; i < 4; i++) {
                int row = 4 * v + i + HALO;
                float val = (i == 0) ? t.x : (i == 1) ? t.y : (i == 2) ? t.z : t.w;
                A[row * TW + 2 * (q ^ swz4(row)) + h] = __float2half(val);
            }
        }
    }
    for (int idx = tid; idx < 2 * HALO * TW; idx += NT) {   // 256 halo elems
        int l = idx & (TW - 1);
        int hh = idx >> 3;
        int t = (hh < HALO) ? (hh - HALO) : (HDIM + hh - HALO);
        int rt = refl(t);
        float val = (ax == 0) ? ip[rt * HDIM + base + l]
                              : ip[(size_t)(base + l) * HDIM + rt];
        int row = t + HALO;
        A[row * TW + 2 * ((l >> 1) ^ swz4(row)) + (l & 1)] = __float2half(val);
    }
    __syncthreads();

    float inv_wsum = 1.0f;
    if (R > 0) {
        float s = 0.f;
        #pragma unroll
        for (int k = 0; k < 31; k++) s += w[k];
        inv_wsum = 1.0f / s;
    }

    // ---- fused blur + downsample -> LOW (fp16, pos-major) ----
    if      (R == 0)  blur_down<0>(A, LOW, w, inv_wsum, res, n_low, tid);
    else if (R == 3)  blur_down<3>(A, LOW, w, inv_wsum, res, n_low, tid);
    else if (R == 7)  blur_down<7>(A, LOW, w, inv_wsum, res, n_low, tid);
    else              blur_down<15>(A, LOW, w, inv_wsum, res, n_low, tid);
    __syncthreads();

    // ---- upsample + gmem stores ----
    if (ax == 0) {
        for (int i = tid; i < HDIM; i += NT) {
            float p2v = pos2[i];
            float l2  = floorf(p2v);
            float f   = p2v - l2;
            int j1 = min((int)l2, n_low - 1);
            int j2 = min(j1 + 1, n_low - 1);
            float omf = 1.0f - f;
            float4 r1 = *(const float4*)(LOW + j1 * TW);   // whole 8-lane row
            float4 r2 = *(const float4*)(LOW + j2 * TW);
            const __half2* h1 = (const __half2*)&r1;
            const __half2* h2 = (const __half2*)&r2;
            float4 o0, o1;
            {
                float2 a = __half22float2(h1[0]), b = __half22float2(h2[0]);
                o0.x = a.x * omf + b.x * f;  o0.y = a.y * omf + b.y * f;
                a = __half22float2(h1[1]); b = __half22float2(h2[1]);
                o0.z = a.x * omf + b.x * f;  o0.w = a.y * omf + b.y * f;
                a = __half22float2(h1[2]); b = __half22float2(h2[2]);
                o1.x = a.x * omf + b.x * f;  o1.y = a.y * omf + b.y * f;
                a = __half22float2(h1[3]); b = __half22float2(h2[3]);
                o1.z = a.x * omf + b.x * f;  o1.w = a.y * omf + b.y * f;
            }
            *(float4*)(op + (size_t)i * HDIM + base)     = o0;
            *(float4*)(op + (size_t)i * HDIM + base + 4) = o1;
        }
    } else {
        for (int idx = tid; idx < 4 * (HDIM / 4); idx += NT) {
            int v  = idx & 127;
            int lq = idx >> 7;              // 0..3 -> lanes 2lq, 2lq+1
            const float4 pv = *(const float4*)(pos2 + 4 * v);
            float4 ra, rb;
            #pragma unroll
            for (int q = 0; q < 4; q++) {
                float p2v = (q == 0) ? pv.x : (q == 1) ? pv.y : (q == 2) ? pv.z : pv.w;
                float l2  = floorf(p2v);
                float f   = p2v - l2;
                int j1 = min((int)l2, n_low - 1);
                int j2 = min(j1 + 1, n_low - 1);
                float2 h1 = __half22float2(*(const __half2*)(LOW + j1 * TW + 2 * lq));
                float2 h2 = __half22float2(*(const __half2*)(LOW + j2 * TW + 2 * lq));
                float va = h1.x * (1.0f - f) + h2.x * f;
                float vb = h1.y * (1.0f - f) + h2.y * f;
                if (q == 0) { ra.x = va; rb.x = vb; }
                else if (q == 1) { ra.y = va; rb.y = vb; }
                else if (q == 2) { ra.z = va; rb.z = vb; }
                else { ra.w = va; rb.w = vb; }
            }
            *(float4*)(op + (size_t)(base + 2 * lq) * HDIM + 4 * v)     = ra;
            *(float4*)(op + (size_t)(base + 2 * lq + 1) * HDIM + 4 * v) = rb;
        }
    }
}

extern "C" void kernel_launch(void* const* d_in, const int* in_sizes, int n_in,
                              void* d_out, int out_size)
{
    const float* x   = (const float*)d_in[0];
    const float* res = (const float*)d_in[1];
    const int*   ax  = (const int*)d_in[2];
    const float* gp  = (const float*)d_in[3];
    float* out = (float*)d_out;

    const int n_img = in_sizes[1];   // 64
    // A(544*8 f16) + LOW(512*8 f16) + pos2(512 f32) + w(32 f32) = 19072 B
    const size_t smem = (size_t)(NROW * TW) * 2 + (size_t)(HDIM * TW) * 2
                      + (size_t)HDIM * 4 + 32 * 4;

    cudaFuncSetAttribute(lowres_kernel,
                         cudaFuncAttributeMaxDynamicSharedMemorySize, (int)smem);

    dim3 grid((HDIM / TW) * n_img);  // 4096 CTAs, image-interleaved
    lowres_kernel<<<grid, NT, smem>>>(x, res, ax, gp, out);
}